// round 9
// baseline (speedup 1.0000x reference)
#include <cuda_runtime.h>
#include <math.h>

#define HIDDEN 640
#define ATTN   128
#define LN_EPS 1e-5f
#define WARPS  8          // warps per CTA in main kernel (256 threads)
#define CHUNKS 64         // chunks per batch (grid.x of main kernel)
#define GSPLIT 8          // k0 split-K groups
#define APERG  (ATTN / GSPLIT)   // 16
#define MAXB   32
#define BSLICE 16         // batches handled per k2b z-slice (smem sizing)
#define MAXZ   8
#define MAXC   128
#define PSTRIDE (HIDDEN + 2)   // per-partial: m, Z, s[640]

// ---- scratch (no allocation allowed) ----
__device__ float g_wpart[MAXB * GSPLIT * HIDDEN];
__device__ float g_w[MAXB * HIDDEN];
__device__ float g_part[(size_t)MAXB * MAXC * PSTRIDE];
__device__ float g_sb[MAXB * HIDDEN];     // normalized pooled-X per batch
__device__ float g_pool[MAXB * HIDDEN];   // pooled after Wv GEMV
// last-CTA fixup counters (zero-init; reset by last consumer each run)
__device__ unsigned int g_cnt0[MAXB];
__device__ unsigned int g_cnt1[MAXB];
__device__ unsigned int g_cnt2[MAXZ];

// ============================================================
// Kernel 0: split-K partial of w[b,h] = scale * sum_a q[b,a] * Wk[a,h].
// grid(B, GSPLIT), block(640). Last CTA per b reduces partials -> g_w.
// ============================================================
__global__ void __launch_bounds__(HIDDEN)
k0_make_w(const float* __restrict__ pos,
          const float* __restrict__ Wq,
          const float* __restrict__ Wk)
{
    __shared__ float ps[HIDDEN];
    __shared__ float qs[APERG];
    __shared__ unsigned int stick;
    const int b    = blockIdx.x;
    const int g    = blockIdx.y;
    const int tid  = threadIdx.x;
    const int wid  = tid >> 5;
    const int lane = tid & 31;
    const int a0   = g * APERG;

    ps[tid] = pos[b * HIDDEN + tid];
    __syncthreads();

    if (wid < APERG) {
        const float4* ps4 = (const float4*)ps;
        const float4* row = (const float4*)(Wq + (size_t)(a0 + wid) * HIDDEN);
        float d = 0.f;
        #pragma unroll
        for (int j = 0; j < 5; j++) {
            const float4 r = row[lane + 32 * j];
            const float4 p = ps4[lane + 32 * j];
            d = fmaf(r.x, p.x, d);
            d = fmaf(r.y, p.y, d);
            d = fmaf(r.z, p.z, d);
            d = fmaf(r.w, p.w, d);
        }
        #pragma unroll
        for (int off = 16; off > 0; off >>= 1)
            d += __shfl_xor_sync(0xffffffffu, d, off);
        if (lane == 0) qs[wid] = d;
    }
    __syncthreads();

    const float scale = rsqrtf((float)ATTN);
    float s = 0.f;
    #pragma unroll
    for (int a = 0; a < APERG; a++)
        s = fmaf(qs[a], Wk[(size_t)(a0 + a) * HIDDEN + tid], s);
    g_wpart[((size_t)b * GSPLIT + g) * HIDDEN + tid] = s * scale;

    // ---- last-CTA fixup: reduce GSPLIT partials (L2-hot) ----
    __threadfence();
    __syncthreads();
    if (tid == 0) stick = atomicAdd(&g_cnt0[b], 1u);
    __syncthreads();
    if (stick == GSPLIT - 1) {
        float r = 0.f;
        #pragma unroll
        for (int gg = 0; gg < GSPLIT; gg++)
            r += __ldcg(&g_wpart[((size_t)b * GSPLIT + gg) * HIDDEN + tid]);
        g_w[b * HIDDEN + tid] = r;
        if (tid == 0) g_cnt0[b] = 0u;   // reset for next replay
    }
}

// ============================================================
// Kernel 1: streaming pass over X with online softmax, 2 tokens/warp-iter.
// grid(CHUNKS, B), block(256) = 8 warps.
// Last CTA per b combines all chunk partials -> normalized g_sb (L2-hot).
// ============================================================
__global__ void __launch_bounds__(WARPS * 32)
k1_stream(const float* __restrict__ X, int N, int chunk)
{
    const int b    = blockIdx.y;
    const int c    = blockIdx.x;
    const int C    = gridDim.x;
    const int tid  = threadIdx.x;
    const int wid  = tid >> 5;
    const int lane = tid & 31;

    float4 w4[5];
    {
        const float4* wb4 = (const float4*)(g_w + b * HIDDEN);
        #pragma unroll
        for (int j = 0; j < 5; j++) w4[j] = wb4[lane + 32 * j];
    }

    const int t0 = c * chunk;
    const int t1 = min(N, t0 + chunk);

    float m = -1e30f, Z = 0.f;
    float4 acc[5];
    #pragma unroll
    for (int j = 0; j < 5; j++) acc[j] = make_float4(0.f, 0.f, 0.f, 0.f);

    for (int t = t0 + 2 * wid; t < t1; t += 2 * WARPS) {
        const bool two = (t + 1 < t1);
        const float4* row0 = (const float4*)(X + ((size_t)b * N + t) * HIDDEN);
        const float4* row1 = (const float4*)(X + ((size_t)b * N + (two ? t + 1 : t)) * HIDDEN);

        float4 r0[5], r1[5];
        #pragma unroll
        for (int j = 0; j < 5; j++) r0[j] = __ldcs(row0 + lane + 32 * j);
        #pragma unroll
        for (int j = 0; j < 5; j++) r1[j] = __ldcs(row1 + lane + 32 * j);

        float d0 = 0.f, d1 = 0.f;
        #pragma unroll
        for (int j = 0; j < 5; j++) {
            d0 = fmaf(r0[j].x, w4[j].x, d0); d1 = fmaf(r1[j].x, w4[j].x, d1);
            d0 = fmaf(r0[j].y, w4[j].y, d0); d1 = fmaf(r1[j].y, w4[j].y, d1);
            d0 = fmaf(r0[j].z, w4[j].z, d0); d1 = fmaf(r1[j].z, w4[j].z, d1);
            d0 = fmaf(r0[j].w, w4[j].w, d0); d1 = fmaf(r1[j].w, w4[j].w, d1);
        }
        #pragma unroll
        for (int off = 16; off > 0; off >>= 1) {
            d0 += __shfl_xor_sync(0xffffffffu, d0, off);
            d1 += __shfl_xor_sync(0xffffffffu, d1, off);
        }

        {
            float p;
            if (d0 > m) {
                const float f = __expf(m - d0);
                Z *= f;
                #pragma unroll
                for (int j = 0; j < 5; j++) {
                    acc[j].x *= f; acc[j].y *= f; acc[j].z *= f; acc[j].w *= f;
                }
                m = d0; p = 1.0f;
            } else p = __expf(d0 - m);
            Z += p;
            #pragma unroll
            for (int j = 0; j < 5; j++) {
                acc[j].x = fmaf(p, r0[j].x, acc[j].x);
                acc[j].y = fmaf(p, r0[j].y, acc[j].y);
                acc[j].z = fmaf(p, r0[j].z, acc[j].z);
                acc[j].w = fmaf(p, r0[j].w, acc[j].w);
            }
        }
        if (two) {
            float p;
            if (d1 > m) {
                const float f = __expf(m - d1);
                Z *= f;
                #pragma unroll
                for (int j = 0; j < 5; j++) {
                    acc[j].x *= f; acc[j].y *= f; acc[j].z *= f; acc[j].w *= f;
                }
                m = d1; p = 1.0f;
            } else p = __expf(d1 - m);
            Z += p;
            #pragma unroll
            for (int j = 0; j < 5; j++) {
                acc[j].x = fmaf(p, r1[j].x, acc[j].x);
                acc[j].y = fmaf(p, r1[j].y, acc[j].y);
                acc[j].z = fmaf(p, r1[j].z, acc[j].z);
                acc[j].w = fmaf(p, r1[j].w, acc[j].w);
            }
        }
    }

    // ---- CTA combine across 8 warps ----
    __shared__ float sm_s[WARPS][HIDDEN];
    __shared__ float sm_m[WARPS], sm_Z[WARPS], sm_f[WARPS];
    __shared__ unsigned int stick;

    {
        float4* srow = (float4*)sm_s[wid];
        #pragma unroll
        for (int j = 0; j < 5; j++) srow[lane + 32 * j] = acc[j];
        if (lane == 0) { sm_m[wid] = m; sm_Z[wid] = Z; }
    }
    __syncthreads();

    if (tid == 0) {
        float M = -1e30f;
        #pragma unroll
        for (int w = 0; w < WARPS; w++) M = fmaxf(M, sm_m[w]);
        float Zt = 0.f;
        #pragma unroll
        for (int w = 0; w < WARPS; w++) {
            const float f = __expf(sm_m[w] - M);
            sm_f[w] = f;
            Zt += f * sm_Z[w];
        }
        float* outp = g_part + ((size_t)b * MAXC + c) * PSTRIDE;
        outp[0] = M; outp[1] = Zt;
    }
    __syncthreads();

    float* outp = g_part + ((size_t)b * MAXC + c) * PSTRIDE;
    for (int h = tid; h < HIDDEN; h += WARPS * 32) {
        float s = 0.f;
        #pragma unroll
        for (int w = 0; w < WARPS; w++) s = fmaf(sm_f[w], sm_s[w][h], s);
        outp[2 + h] = s;
    }

    // ---- last-CTA fixup: full softmax combine for batch b (L2-hot) ----
    __threadfence();
    __syncthreads();
    if (tid == 0) stick = atomicAdd(&g_cnt1[b], 1u);
    __syncthreads();
    if (stick == (unsigned int)(C - 1)) {
        __shared__ float sfc[MAXC];
        __shared__ float sZc;
        const float* pbase = g_part + (size_t)b * MAXC * PSTRIDE;

        if (wid == 0) {
            float m0 = -1e30f, m1 = -1e30f;
            if (lane < C)      m0 = __ldcg(&pbase[(size_t)lane * PSTRIDE]);
            if (lane + 32 < C) m1 = __ldcg(&pbase[(size_t)(lane + 32) * PSTRIDE]);
            float M = fmaxf(m0, m1);
            #pragma unroll
            for (int off = 16; off > 0; off >>= 1)
                M = fmaxf(M, __shfl_xor_sync(0xffffffffu, M, off));

            float z = 0.f;
            if (lane < C) {
                const float f = __expf(m0 - M);
                sfc[lane] = f;
                z += f * __ldcg(&pbase[(size_t)lane * PSTRIDE + 1]);
            }
            if (lane + 32 < C) {
                const float f = __expf(m1 - M);
                sfc[lane + 32] = f;
                z += f * __ldcg(&pbase[(size_t)(lane + 32) * PSTRIDE + 1]);
            }
            #pragma unroll
            for (int off = 16; off > 0; off >>= 1)
                z += __shfl_xor_sync(0xffffffffu, z, off);
            if (lane == 0) sZc = z;
        }
        __syncthreads();

        const float invZ = 1.0f / sZc;
        for (int h = tid; h < HIDDEN; h += WARPS * 32) {
            float s = 0.f;
            #pragma unroll 8
            for (int cc = 0; cc < C; cc++)
                s = fmaf(sfc[cc], __ldcg(&pbase[(size_t)cc * PSTRIDE + 2 + h]), s);
            g_sb[b * HIDDEN + h] = s * invZ;
        }
        if (tid == 0) g_cnt1[b] = 0u;   // reset for next replay
    }
}

// ============================================================
// Kernel 2b: pooled[b][v] = g_sb[b] . Wv[v] for all b; last CTA per
// z-slice does the LayerNorm + output store (L2-hot).
// grid(HIDDEN/8, 1, ceil(B/BSLICE)), block(256) = 8 warps, warp-per-row.
// ============================================================
__global__ void __launch_bounds__(256)
k2b_gemv_ln(const float* __restrict__ Wv,
            const float* __restrict__ gamma,
            const float* __restrict__ beta,
            float* __restrict__ out, int B)
{
    __shared__ float sb_sm[BSLICE * HIDDEN];   // 40 KB
    __shared__ unsigned int stick;

    const int tid  = threadIdx.x;
    const int wid  = tid >> 5;
    const int lane = tid & 31;
    const int b0   = blockIdx.z * BSLICE;
    const int nb   = min(BSLICE, B - b0);
    const int v    = blockIdx.x * 8 + wid;

    for (int i = tid; i < nb * HIDDEN; i += 256)
        sb_sm[i] = g_sb[(size_t)b0 * HIDDEN + i];
    __syncthreads();

    float4 r[5];
    {
        const float4* wr = (const float4*)(Wv + (size_t)v * HIDDEN);
        #pragma unroll
        for (int j = 0; j < 5; j++) r[j] = wr[lane + 32 * j];
    }

    for (int b = 0; b < nb; b += 2) {
        const bool two = (b + 1 < nb);
        const float4* s0 = (const float4*)(sb_sm + (size_t)b * HIDDEN);
        const float4* s1 = (const float4*)(sb_sm + (size_t)(two ? b + 1 : b) * HIDDEN);
        float d0 = 0.f, d1 = 0.f;
        #pragma unroll
        for (int j = 0; j < 5; j++) {
            const float4 a0 = s0[lane + 32 * j];
            const float4 a1 = s1[lane + 32 * j];
            d0 = fmaf(r[j].x, a0.x, d0); d1 = fmaf(r[j].x, a1.x, d1);
            d0 = fmaf(r[j].y, a0.y, d0); d1 = fmaf(r[j].y, a1.y, d1);
            d0 = fmaf(r[j].z, a0.z, d0); d1 = fmaf(r[j].z, a1.z, d1);
            d0 = fmaf(r[j].w, a0.w, d0); d1 = fmaf(r[j].w, a1.w, d1);
        }
        #pragma unroll
        for (int off = 16; off > 0; off >>= 1) {
            d0 += __shfl_xor_sync(0xffffffffu, d0, off);
            d1 += __shfl_xor_sync(0xffffffffu, d1, off);
        }
        if (lane == 0) {
            g_pool[(size_t)(b0 + b) * HIDDEN + v] = d0;
            if (two) g_pool[(size_t)(b0 + b + 1) * HIDDEN + v] = d1;
        }
    }

    // ---- last-CTA fixup: LayerNorm + store (warp-per-batch, L2-hot) ----
    __threadfence();
    __syncthreads();
    if (tid == 0) stick = atomicAdd(&g_cnt2[blockIdx.z], 1u);
    __syncthreads();
    if (stick == gridDim.x - 1) {
        for (int bb = wid; bb < nb; bb += 8) {
            const int b = b0 + bb;
            float xv[HIDDEN / 32];
            float s = 0.f, q = 0.f;
            #pragma unroll
            for (int i = 0; i < HIDDEN / 32; i++) {
                xv[i] = __ldcg(&g_pool[(size_t)b * HIDDEN + lane + 32 * i]);
                s += xv[i];
                q = fmaf(xv[i], xv[i], q);
            }
            #pragma unroll
            for (int off = 16; off > 0; off >>= 1) {
                s += __shfl_xor_sync(0xffffffffu, s, off);
                q += __shfl_xor_sync(0xffffffffu, q, off);
            }
            const float mu   = s / (float)HIDDEN;
            const float var  = q / (float)HIDDEN - mu * mu;
            const float rstd = rsqrtf(var + LN_EPS);
            #pragma unroll
            for (int i = 0; i < HIDDEN / 32; i++) {
                const int h = lane + 32 * i;
                out[(size_t)b * HIDDEN + h] =
                    (xv[i] - mu) * rstd * gamma[h] + beta[h];
            }
        }
        if (tid == 0) g_cnt2[blockIdx.z] = 0u;   // reset for next replay
    }
}

// ============================================================
extern "C" void kernel_launch(void* const* d_in, const int* in_sizes, int n_in,
                              void* d_out, int out_size)
{
    const float* X     = (const float*)d_in[0];
    const float* pos   = (const float*)d_in[1];
    const float* Wq    = (const float*)d_in[2];
    const float* Wk    = (const float*)d_in[3];
    const float* Wv    = (const float*)d_in[4];
    const float* gamma = (const float*)d_in[5];
    const float* beta  = (const float*)d_in[6];
    float* out = (float*)d_out;

    const int B = in_sizes[1] / HIDDEN;
    const int N = in_sizes[0] / (B * HIDDEN);
    const int C = CHUNKS;
    const int chunk = (N + C - 1) / C;

    dim3 g0(B, GSPLIT);
    k0_make_w<<<g0, HIDDEN>>>(pos, Wq, Wk);
    dim3 g1(C, B);
    k1_stream<<<g1, WARPS * 32>>>(X, N, chunk);
    dim3 g2b(HIDDEN / 8, 1, (B + BSLICE - 1) / BSLICE);
    k2b_gemv_ln<<<g2b, 256>>>(Wv, gamma, beta, out, B);
}

// round 14
// speedup vs baseline: 1.0585x; 1.0585x over previous
#include <cuda_runtime.h>
#include <math.h>

#define HIDDEN 640
#define ATTN   128
#define LN_EPS 1e-5f
#define WARPS  8          // warps per CTA in main kernel (256 threads)
#define CHUNKS 64         // chunks per batch (grid.x of main kernel)
#define GSPLIT 8          // k0 split-K groups
#define APERG  (ATTN / GSPLIT)   // 16
#define CSPLIT 8          // k2a split groups
#define CPG    (CHUNKS / CSPLIT) // 8 chunks per k2a1 CTA
#define MAXB   32
#define BSLICE 16         // batches handled per k2b z-slice (smem sizing)
#define MAXZ   8
#define MAXC   128
// partial layout: s[0..640) | m @640 | Z @641, padded to 644 for float4 align
#define PSTRIDE 644

// ---- scratch (no allocation allowed) ----
__device__ float g_wpart[MAXB * GSPLIT * HIDDEN];
__device__ float g_w[MAXB * HIDDEN];
__device__ __align__(16) float g_part[(size_t)MAXB * MAXC * PSTRIDE];
__device__ float g_sbpart[MAXB * CSPLIT * HIDDEN];
__device__ float g_sb[MAXB * HIDDEN];     // normalized pooled-X per batch
__device__ float g_pool[MAXB * HIDDEN];   // pooled after Wv GEMV
// last-CTA fixup counters (zero-init; reset by last consumer each run)
__device__ unsigned int g_cnt0[MAXB];
__device__ unsigned int g_cnt2[MAXZ];

// ============================================================
// Kernel 0: split-K partial of w[b,h] = scale * sum_a q[b,a] * Wk[a,h].
// grid(B, GSPLIT), block(640). Last CTA per b reduces partials -> g_w.
// ============================================================
__global__ void __launch_bounds__(HIDDEN)
k0_make_w(const float* __restrict__ pos,
          const float* __restrict__ Wq,
          const float* __restrict__ Wk)
{
    __shared__ float ps[HIDDEN];
    __shared__ float qs[APERG];
    __shared__ unsigned int stick;
    const int b    = blockIdx.x;
    const int g    = blockIdx.y;
    const int tid  = threadIdx.x;
    const int wid  = tid >> 5;
    const int lane = tid & 31;
    const int a0   = g * APERG;

    ps[tid] = pos[b * HIDDEN + tid];
    __syncthreads();

    if (wid < APERG) {
        const float4* ps4 = (const float4*)ps;
        const float4* row = (const float4*)(Wq + (size_t)(a0 + wid) * HIDDEN);
        float d = 0.f;
        #pragma unroll
        for (int j = 0; j < 5; j++) {
            const float4 r = row[lane + 32 * j];
            const float4 p = ps4[lane + 32 * j];
            d = fmaf(r.x, p.x, d);
            d = fmaf(r.y, p.y, d);
            d = fmaf(r.z, p.z, d);
            d = fmaf(r.w, p.w, d);
        }
        #pragma unroll
        for (int off = 16; off > 0; off >>= 1)
            d += __shfl_xor_sync(0xffffffffu, d, off);
        if (lane == 0) qs[wid] = d;
    }
    __syncthreads();

    const float scale = rsqrtf((float)ATTN);
    float s = 0.f;
    #pragma unroll
    for (int a = 0; a < APERG; a++)
        s = fmaf(qs[a], Wk[(size_t)(a0 + a) * HIDDEN + tid], s);
    g_wpart[((size_t)b * GSPLIT + g) * HIDDEN + tid] = s * scale;

    // ---- last-CTA fixup: reduce GSPLIT partials (L2-hot) ----
    __threadfence();
    __syncthreads();
    if (tid == 0) stick = atomicAdd(&g_cnt0[b], 1u);
    __syncthreads();
    if (stick == GSPLIT - 1) {
        float r = 0.f;
        #pragma unroll
        for (int gg = 0; gg < GSPLIT; gg++)
            r += __ldcg(&g_wpart[((size_t)b * GSPLIT + gg) * HIDDEN + tid]);
        g_w[b * HIDDEN + tid] = r;
        if (tid == 0) g_cnt0[b] = 0u;   // reset for next replay
    }
}

// ============================================================
// Kernel 1: streaming pass over X with online softmax, 2 tokens/warp-iter.
// grid(CHUNKS, B), block(256) = 8 warps. Pure: writes partials only.
// ============================================================
__global__ void __launch_bounds__(WARPS * 32)
k1_stream(const float* __restrict__ X, int N, int chunk)
{
    const int b    = blockIdx.y;
    const int c    = blockIdx.x;
    const int tid  = threadIdx.x;
    const int wid  = tid >> 5;
    const int lane = tid & 31;

    float4 w4[5];
    {
        const float4* wb4 = (const float4*)(g_w + b * HIDDEN);
        #pragma unroll
        for (int j = 0; j < 5; j++) w4[j] = wb4[lane + 32 * j];
    }

    const int t0 = c * chunk;
    const int t1 = min(N, t0 + chunk);

    float m = -1e30f, Z = 0.f;
    float4 acc[5];
    #pragma unroll
    for (int j = 0; j < 5; j++) acc[j] = make_float4(0.f, 0.f, 0.f, 0.f);

    for (int t = t0 + 2 * wid; t < t1; t += 2 * WARPS) {
        const bool two = (t + 1 < t1);
        const float4* row0 = (const float4*)(X + ((size_t)b * N + t) * HIDDEN);
        const float4* row1 = (const float4*)(X + ((size_t)b * N + (two ? t + 1 : t)) * HIDDEN);

        float4 r0[5], r1[5];
        #pragma unroll
        for (int j = 0; j < 5; j++) r0[j] = __ldcs(row0 + lane + 32 * j);
        #pragma unroll
        for (int j = 0; j < 5; j++) r1[j] = __ldcs(row1 + lane + 32 * j);

        float d0 = 0.f, d1 = 0.f;
        #pragma unroll
        for (int j = 0; j < 5; j++) {
            d0 = fmaf(r0[j].x, w4[j].x, d0); d1 = fmaf(r1[j].x, w4[j].x, d1);
            d0 = fmaf(r0[j].y, w4[j].y, d0); d1 = fmaf(r1[j].y, w4[j].y, d1);
            d0 = fmaf(r0[j].z, w4[j].z, d0); d1 = fmaf(r1[j].z, w4[j].z, d1);
            d0 = fmaf(r0[j].w, w4[j].w, d0); d1 = fmaf(r1[j].w, w4[j].w, d1);
        }
        #pragma unroll
        for (int off = 16; off > 0; off >>= 1) {
            d0 += __shfl_xor_sync(0xffffffffu, d0, off);
            d1 += __shfl_xor_sync(0xffffffffu, d1, off);
        }

        {
            float p;
            if (d0 > m) {
                const float f = __expf(m - d0);
                Z *= f;
                #pragma unroll
                for (int j = 0; j < 5; j++) {
                    acc[j].x *= f; acc[j].y *= f; acc[j].z *= f; acc[j].w *= f;
                }
                m = d0; p = 1.0f;
            } else p = __expf(d0 - m);
            Z += p;
            #pragma unroll
            for (int j = 0; j < 5; j++) {
                acc[j].x = fmaf(p, r0[j].x, acc[j].x);
                acc[j].y = fmaf(p, r0[j].y, acc[j].y);
                acc[j].z = fmaf(p, r0[j].z, acc[j].z);
                acc[j].w = fmaf(p, r0[j].w, acc[j].w);
            }
        }
        if (two) {
            float p;
            if (d1 > m) {
                const float f = __expf(m - d1);
                Z *= f;
                #pragma unroll
                for (int j = 0; j < 5; j++) {
                    acc[j].x *= f; acc[j].y *= f; acc[j].z *= f; acc[j].w *= f;
                }
                m = d1; p = 1.0f;
            } else p = __expf(d1 - m);
            Z += p;
            #pragma unroll
            for (int j = 0; j < 5; j++) {
                acc[j].x = fmaf(p, r1[j].x, acc[j].x);
                acc[j].y = fmaf(p, r1[j].y, acc[j].y);
                acc[j].z = fmaf(p, r1[j].z, acc[j].z);
                acc[j].w = fmaf(p, r1[j].w, acc[j].w);
            }
        }
    }

    // ---- CTA combine across 8 warps ----
    __shared__ float sm_s[WARPS][HIDDEN];
    __shared__ float sm_m[WARPS], sm_Z[WARPS], sm_f[WARPS];

    {
        float4* srow = (float4*)sm_s[wid];
        #pragma unroll
        for (int j = 0; j < 5; j++) srow[lane + 32 * j] = acc[j];
        if (lane == 0) { sm_m[wid] = m; sm_Z[wid] = Z; }
    }
    __syncthreads();

    float* outp = g_part + ((size_t)b * MAXC + c) * PSTRIDE;

    if (tid == 0) {
        float M = -1e30f;
        #pragma unroll
        for (int w = 0; w < WARPS; w++) M = fmaxf(M, sm_m[w]);
        float Zt = 0.f;
        #pragma unroll
        for (int w = 0; w < WARPS; w++) {
            const float f = __expf(sm_m[w] - M);
            sm_f[w] = f;
            Zt += f * sm_Z[w];
        }
        outp[640] = M; outp[641] = Zt;
    }
    __syncthreads();

    for (int h = tid; h < HIDDEN; h += WARPS * 32) {
        float s = 0.f;
        #pragma unroll
        for (int w = 0; w < WARPS; w++) s = fmaf(sm_f[w], sm_s[w][h], s);
        outp[h] = s;
    }
}

// ============================================================
// Kernel 2a1: per-(b,cs) partial combine of CPG chunks, float4-coalesced.
// grid(B, CSPLIT), block(640) = 160 h-groups x 4 c-groups.
// ============================================================
__global__ void __launch_bounds__(HIDDEN)
k2a1_partial(int C)
{
    const int b    = blockIdx.x;
    const int cs   = blockIdx.y;
    const int tid  = threadIdx.x;
    const int wid  = tid >> 5;
    const int lane = tid & 31;
    const int hg   = tid % 160;    // h-group: covers h = 4*hg .. 4*hg+3
    const int cg   = tid / 160;    // 0..3: chunk sub-group (CPG/4 = 2 chunks each)

    __shared__ float sf[CPG];
    __shared__ float4 red[4][160];

    const float* pbase = g_part + (size_t)b * MAXC * PSTRIDE;

    // warp 0: global max over all C chunk maxima, then f for this group's chunks
    if (wid == 0) {
        float m0 = -1e30f, m1 = -1e30f;
        if (lane < C)      m0 = pbase[(size_t)lane * PSTRIDE + 640];
        if (lane + 32 < C) m1 = pbase[(size_t)(lane + 32) * PSTRIDE + 640];
        float M = fmaxf(m0, m1);
        #pragma unroll
        for (int off = 16; off > 0; off >>= 1)
            M = fmaxf(M, __shfl_xor_sync(0xffffffffu, M, off));
        if (lane < CPG) {
            const float mc = pbase[(size_t)(cs * CPG + lane) * PSTRIDE + 640];
            sf[lane] = __expf(mc - M);
        }
    }
    __syncthreads();

    // each thread: float4 partial over its 2 chunks, fully coalesced
    float4 s = make_float4(0.f, 0.f, 0.f, 0.f);
    #pragma unroll
    for (int k = 0; k < CPG / 4; k++) {
        const int cl = cg * (CPG / 4) + k;
        const float f = sf[cl];
        const float4 v = *(const float4*)&pbase[(size_t)(cs * CPG + cl) * PSTRIDE + 4 * hg];
        s.x = fmaf(f, v.x, s.x);
        s.y = fmaf(f, v.y, s.y);
        s.z = fmaf(f, v.z, s.z);
        s.w = fmaf(f, v.w, s.w);
    }
    red[cg][hg] = s;
    __syncthreads();

    // c-group 0 threads reduce 4 partials and store
    if (tid < 160) {
        float4 a0 = red[0][tid], a1 = red[1][tid], a2 = red[2][tid], a3 = red[3][tid];
        a0.x += a1.x + a2.x + a3.x;
        a0.y += a1.y + a2.y + a3.y;
        a0.z += a1.z + a2.z + a3.z;
        a0.w += a1.w + a2.w + a3.w;
        *(float4*)&g_sbpart[((size_t)b * CSPLIT + cs) * HIDDEN + 4 * tid] = a0;
    }
}

// ============================================================
// Kernel 2a2: reduce CSPLIT partials, normalize by Z. grid(B), block(640).
// ============================================================
__global__ void __launch_bounds__(HIDDEN)
k2a2_reduce(int C)
{
    const int b    = blockIdx.x;
    const int tid  = threadIdx.x;
    const int wid  = tid >> 5;
    const int lane = tid & 31;

    __shared__ float sZ;

    const float* pbase = g_part + (size_t)b * MAXC * PSTRIDE;

    if (wid == 0) {
        float m0 = -1e30f, m1 = -1e30f;
        if (lane < C)      m0 = pbase[(size_t)lane * PSTRIDE + 640];
        if (lane + 32 < C) m1 = pbase[(size_t)(lane + 32) * PSTRIDE + 640];
        float M = fmaxf(m0, m1);
        #pragma unroll
        for (int off = 16; off > 0; off >>= 1)
            M = fmaxf(M, __shfl_xor_sync(0xffffffffu, M, off));

        float z = 0.f;
        if (lane < C)      z += __expf(m0 - M) * pbase[(size_t)lane * PSTRIDE + 641];
        if (lane + 32 < C) z += __expf(m1 - M) * pbase[(size_t)(lane + 32) * PSTRIDE + 641];
        #pragma unroll
        for (int off = 16; off > 0; off >>= 1)
            z += __shfl_xor_sync(0xffffffffu, z, off);
        if (lane == 0) sZ = z;
    }
    __syncthreads();

    const float invZ = 1.0f / sZ;
    float s = 0.f;
    #pragma unroll
    for (int g = 0; g < CSPLIT; g++)
        s += g_sbpart[((size_t)b * CSPLIT + g) * HIDDEN + tid];
    g_sb[b * HIDDEN + tid] = s * invZ;
}

// ============================================================
// Kernel 2b: pooled[b][v] = g_sb[b] . Wv[v] for all b; last CTA per
// z-slice does the LayerNorm + output store (L2-hot).
// grid(HIDDEN/8, 1, ceil(B/BSLICE)), block(256) = 8 warps, warp-per-row.
// ============================================================
__global__ void __launch_bounds__(256)
k2b_gemv_ln(const float* __restrict__ Wv,
            const float* __restrict__ gamma,
            const float* __restrict__ beta,
            float* __restrict__ out, int B)
{
    __shared__ float sb_sm[BSLICE * HIDDEN];   // 40 KB
    __shared__ unsigned int stick;

    const int tid  = threadIdx.x;
    const int wid  = tid >> 5;
    const int lane = tid & 31;
    const int b0   = blockIdx.z * BSLICE;
    const int nb   = min(BSLICE, B - b0);
    const int v    = blockIdx.x * 8 + wid;

    for (int i = tid; i < nb * HIDDEN; i += 256)
        sb_sm[i] = g_sb[(size_t)b0 * HIDDEN + i];
    __syncthreads();

    float4 r[5];
    {
        const float4* wr = (const float4*)(Wv + (size_t)v * HIDDEN);
        #pragma unroll
        for (int j = 0; j < 5; j++) r[j] = wr[lane + 32 * j];
    }

    for (int b = 0; b < nb; b += 2) {
        const bool two = (b + 1 < nb);
        const float4* s0 = (const float4*)(sb_sm + (size_t)b * HIDDEN);
        const float4* s1 = (const float4*)(sb_sm + (size_t)(two ? b + 1 : b) * HIDDEN);
        float d0 = 0.f, d1 = 0.f;
        #pragma unroll
        for (int j = 0; j < 5; j++) {
            const float4 a0 = s0[lane + 32 * j];
            const float4 a1 = s1[lane + 32 * j];
            d0 = fmaf(r[j].x, a0.x, d0); d1 = fmaf(r[j].x, a1.x, d1);
            d0 = fmaf(r[j].y, a0.y, d0); d1 = fmaf(r[j].y, a1.y, d1);
            d0 = fmaf(r[j].z, a0.z, d0); d1 = fmaf(r[j].z, a1.z, d1);
            d0 = fmaf(r[j].w, a0.w, d0); d1 = fmaf(r[j].w, a1.w, d1);
        }
        #pragma unroll
        for (int off = 16; off > 0; off >>= 1) {
            d0 += __shfl_xor_sync(0xffffffffu, d0, off);
            d1 += __shfl_xor_sync(0xffffffffu, d1, off);
        }
        if (lane == 0) {
            g_pool[(size_t)(b0 + b) * HIDDEN + v] = d0;
            if (two) g_pool[(size_t)(b0 + b + 1) * HIDDEN + v] = d1;
        }
    }

    // ---- last-CTA fixup: LayerNorm + store (warp-per-batch, L2-hot) ----
    __threadfence();
    __syncthreads();
    if (tid == 0) stick = atomicAdd(&g_cnt2[blockIdx.z], 1u);
    __syncthreads();
    if (stick == gridDim.x - 1) {
        for (int bb = wid; bb < nb; bb += 8) {
            const int b = b0 + bb;
            float xv[HIDDEN / 32];
            float s = 0.f, q = 0.f;
            #pragma unroll
            for (int i = 0; i < HIDDEN / 32; i++) {
                xv[i] = __ldcg(&g_pool[(size_t)b * HIDDEN + lane + 32 * i]);
                s += xv[i];
                q = fmaf(xv[i], xv[i], q);
            }
            #pragma unroll
            for (int off = 16; off > 0; off >>= 1) {
                s += __shfl_xor_sync(0xffffffffu, s, off);
                q += __shfl_xor_sync(0xffffffffu, q, off);
            }
            const float mu   = s / (float)HIDDEN;
            const float var  = q / (float)HIDDEN - mu * mu;
            const float rstd = rsqrtf(var + LN_EPS);
            #pragma unroll
            for (int i = 0; i < HIDDEN / 32; i++) {
                const int h = lane + 32 * i;
                out[(size_t)b * HIDDEN + h] =
                    (xv[i] - mu) * rstd * gamma[h] + beta[h];
            }
        }
        if (tid == 0) g_cnt2[blockIdx.z] = 0u;   // reset for next replay
    }
}

// ============================================================
extern "C" void kernel_launch(void* const* d_in, const int* in_sizes, int n_in,
                              void* d_out, int out_size)
{
    const float* X     = (const float*)d_in[0];
    const float* pos   = (const float*)d_in[1];
    const float* Wq    = (const float*)d_in[2];
    const float* Wk    = (const float*)d_in[3];
    const float* Wv    = (const float*)d_in[4];
    const float* gamma = (const float*)d_in[5];
    const float* beta  = (const float*)d_in[6];
    float* out = (float*)d_out;

    const int B = in_sizes[1] / HIDDEN;
    const int N = in_sizes[0] / (B * HIDDEN);
    const int C = CHUNKS;
    const int chunk = (N + C - 1) / C;

    dim3 g0(B, GSPLIT);
    k0_make_w<<<g0, HIDDEN>>>(pos, Wq, Wk);
    dim3 g1(C, B);
    k1_stream<<<g1, WARPS * 32>>>(X, N, chunk);
    dim3 g2a(B, CSPLIT);
    k2a1_partial<<<g2a, HIDDEN>>>(C);
    k2a2_reduce<<<B, HIDDEN>>>(C);
    dim3 g2b(HIDDEN / 8, 1, (B + BSLICE - 1) / BSLICE);
    k2b_gemv_ln<<<g2b, 256>>>(Wv, gamma, beta, out, B);
}

// round 15
// speedup vs baseline: 1.0672x; 1.0082x over previous
#include <cuda_runtime.h>
#include <math.h>

#define HIDDEN 640
#define ATTN   128
#define LN_EPS 1e-5f
#define WARPS  8          // warps per CTA in main kernel (256 threads)
#define CHUNKS 64         // chunks per batch (grid.x of main kernel)
#define GSPLIT 8          // k0 split-K groups
#define APERG  (ATTN / GSPLIT)   // 16
#define CSPLIT 8          // k2a split groups
#define CPG    (CHUNKS / CSPLIT) // 8 chunks per k2a1 CTA
#define MAXB   32
#define BSLICE 16         // batches handled per k2b z-slice (smem sizing)
#define MAXZ   8
#define MAXC   128
// partial layout: s[0..640) | m @640 | Z @641, padded to 644 for float4 align
#define PSTRIDE 644

// ---- scratch (no allocation allowed) ----
__device__ float g_wpart[MAXB * GSPLIT * HIDDEN];
__device__ float g_w[MAXB * HIDDEN];
__device__ __align__(16) float g_part[(size_t)MAXB * MAXC * PSTRIDE];
__device__ float g_sbpart[MAXB * CSPLIT * HIDDEN];
__device__ float g_sb[MAXB * HIDDEN];     // normalized pooled-X per batch
__device__ float g_pool[MAXB * HIDDEN];   // pooled after Wv GEMV
// last-CTA fixup counters (zero-init; reset by last consumer each run)
__device__ unsigned int g_cnt0[MAXB];
__device__ unsigned int g_cnt1[MAXB];
__device__ unsigned int g_cnt2[MAXZ];

// ============================================================
// Kernel 0: split-K partial of w[b,h] = scale * sum_a q[b,a] * Wk[a,h].
// grid(B, GSPLIT), block(640). Last CTA per b reduces partials -> g_w.
// ============================================================
__global__ void __launch_bounds__(HIDDEN)
k0_make_w(const float* __restrict__ pos,
          const float* __restrict__ Wq,
          const float* __restrict__ Wk)
{
    __shared__ float ps[HIDDEN];
    __shared__ float qs[APERG];
    __shared__ unsigned int stick;
    const int b    = blockIdx.x;
    const int g    = blockIdx.y;
    const int tid  = threadIdx.x;
    const int wid  = tid >> 5;
    const int lane = tid & 31;
    const int a0   = g * APERG;

    ps[tid] = pos[b * HIDDEN + tid];
    __syncthreads();

    if (wid < APERG) {
        const float4* ps4 = (const float4*)ps;
        const float4* row = (const float4*)(Wq + (size_t)(a0 + wid) * HIDDEN);
        float d = 0.f;
        #pragma unroll
        for (int j = 0; j < 5; j++) {
            const float4 r = row[lane + 32 * j];
            const float4 p = ps4[lane + 32 * j];
            d = fmaf(r.x, p.x, d);
            d = fmaf(r.y, p.y, d);
            d = fmaf(r.z, p.z, d);
            d = fmaf(r.w, p.w, d);
        }
        #pragma unroll
        for (int off = 16; off > 0; off >>= 1)
            d += __shfl_xor_sync(0xffffffffu, d, off);
        if (lane == 0) qs[wid] = d;
    }
    __syncthreads();

    const float scale = rsqrtf((float)ATTN);
    float s = 0.f;
    #pragma unroll
    for (int a = 0; a < APERG; a++)
        s = fmaf(qs[a], Wk[(size_t)(a0 + a) * HIDDEN + tid], s);
    g_wpart[((size_t)b * GSPLIT + g) * HIDDEN + tid] = s * scale;

    // ---- last-CTA fixup: reduce GSPLIT partials (L2-hot) ----
    __threadfence();
    __syncthreads();
    if (tid == 0) stick = atomicAdd(&g_cnt0[b], 1u);
    __syncthreads();
    if (stick == GSPLIT - 1) {
        float r = 0.f;
        #pragma unroll
        for (int gg = 0; gg < GSPLIT; gg++)
            r += __ldcg(&g_wpart[((size_t)b * GSPLIT + gg) * HIDDEN + tid]);
        g_w[b * HIDDEN + tid] = r;
        if (tid == 0) g_cnt0[b] = 0u;   // reset for next replay
    }
}

// ============================================================
// Kernel 1: streaming pass over X with online softmax, 2 tokens/warp-iter.
// grid(CHUNKS, B), block(256) = 8 warps. Pure: writes partials only.
// ============================================================
__global__ void __launch_bounds__(WARPS * 32)
k1_stream(const float* __restrict__ X, int N, int chunk)
{
    const int b    = blockIdx.y;
    const int c    = blockIdx.x;
    const int tid  = threadIdx.x;
    const int wid  = tid >> 5;
    const int lane = tid & 31;

    float4 w4[5];
    {
        const float4* wb4 = (const float4*)(g_w + b * HIDDEN);
        #pragma unroll
        for (int j = 0; j < 5; j++) w4[j] = wb4[lane + 32 * j];
    }

    const int t0 = c * chunk;
    const int t1 = min(N, t0 + chunk);

    float m = -1e30f, Z = 0.f;
    float4 acc[5];
    #pragma unroll
    for (int j = 0; j < 5; j++) acc[j] = make_float4(0.f, 0.f, 0.f, 0.f);

    for (int t = t0 + 2 * wid; t < t1; t += 2 * WARPS) {
        const bool two = (t + 1 < t1);
        const float4* row0 = (const float4*)(X + ((size_t)b * N + t) * HIDDEN);
        const float4* row1 = (const float4*)(X + ((size_t)b * N + (two ? t + 1 : t)) * HIDDEN);

        float4 r0[5], r1[5];
        #pragma unroll
        for (int j = 0; j < 5; j++) r0[j] = __ldcs(row0 + lane + 32 * j);
        #pragma unroll
        for (int j = 0; j < 5; j++) r1[j] = __ldcs(row1 + lane + 32 * j);

        float d0 = 0.f, d1 = 0.f;
        #pragma unroll
        for (int j = 0; j < 5; j++) {
            d0 = fmaf(r0[j].x, w4[j].x, d0); d1 = fmaf(r1[j].x, w4[j].x, d1);
            d0 = fmaf(r0[j].y, w4[j].y, d0); d1 = fmaf(r1[j].y, w4[j].y, d1);
            d0 = fmaf(r0[j].z, w4[j].z, d0); d1 = fmaf(r1[j].z, w4[j].z, d1);
            d0 = fmaf(r0[j].w, w4[j].w, d0); d1 = fmaf(r1[j].w, w4[j].w, d1);
        }
        #pragma unroll
        for (int off = 16; off > 0; off >>= 1) {
            d0 += __shfl_xor_sync(0xffffffffu, d0, off);
            d1 += __shfl_xor_sync(0xffffffffu, d1, off);
        }

        {
            float p;
            if (d0 > m) {
                const float f = __expf(m - d0);
                Z *= f;
                #pragma unroll
                for (int j = 0; j < 5; j++) {
                    acc[j].x *= f; acc[j].y *= f; acc[j].z *= f; acc[j].w *= f;
                }
                m = d0; p = 1.0f;
            } else p = __expf(d0 - m);
            Z += p;
            #pragma unroll
            for (int j = 0; j < 5; j++) {
                acc[j].x = fmaf(p, r0[j].x, acc[j].x);
                acc[j].y = fmaf(p, r0[j].y, acc[j].y);
                acc[j].z = fmaf(p, r0[j].z, acc[j].z);
                acc[j].w = fmaf(p, r0[j].w, acc[j].w);
            }
        }
        if (two) {
            float p;
            if (d1 > m) {
                const float f = __expf(m - d1);
                Z *= f;
                #pragma unroll
                for (int j = 0; j < 5; j++) {
                    acc[j].x *= f; acc[j].y *= f; acc[j].z *= f; acc[j].w *= f;
                }
                m = d1; p = 1.0f;
            } else p = __expf(d1 - m);
            Z += p;
            #pragma unroll
            for (int j = 0; j < 5; j++) {
                acc[j].x = fmaf(p, r1[j].x, acc[j].x);
                acc[j].y = fmaf(p, r1[j].y, acc[j].y);
                acc[j].z = fmaf(p, r1[j].z, acc[j].z);
                acc[j].w = fmaf(p, r1[j].w, acc[j].w);
            }
        }
    }

    // ---- CTA combine across 8 warps ----
    __shared__ float sm_s[WARPS][HIDDEN];
    __shared__ float sm_m[WARPS], sm_Z[WARPS], sm_f[WARPS];

    {
        float4* srow = (float4*)sm_s[wid];
        #pragma unroll
        for (int j = 0; j < 5; j++) srow[lane + 32 * j] = acc[j];
        if (lane == 0) { sm_m[wid] = m; sm_Z[wid] = Z; }
    }
    __syncthreads();

    float* outp = g_part + ((size_t)b * MAXC + c) * PSTRIDE;

    if (tid == 0) {
        float M = -1e30f;
        #pragma unroll
        for (int w = 0; w < WARPS; w++) M = fmaxf(M, sm_m[w]);
        float Zt = 0.f;
        #pragma unroll
        for (int w = 0; w < WARPS; w++) {
            const float f = __expf(sm_m[w] - M);
            sm_f[w] = f;
            Zt += f * sm_Z[w];
        }
        outp[640] = M; outp[641] = Zt;
    }
    __syncthreads();

    for (int h = tid; h < HIDDEN; h += WARPS * 32) {
        float s = 0.f;
        #pragma unroll
        for (int w = 0; w < WARPS; w++) s = fmaf(sm_f[w], sm_s[w][h], s);
        outp[h] = s;
    }
}

// ============================================================
// Kernel 2a1: per-(b,cs) partial combine of CPG chunks, float4-coalesced.
// grid(B, CSPLIT), block(640) = 160 h-groups x 4 c-groups.
// Last CTA per b reduces the CSPLIT partials + normalizes -> g_sb (L2-hot).
// ============================================================
__global__ void __launch_bounds__(HIDDEN)
k2a1_partial(int C)
{
    const int b    = blockIdx.x;
    const int cs   = blockIdx.y;
    const int tid  = threadIdx.x;
    const int wid  = tid >> 5;
    const int lane = tid & 31;
    const int hg   = tid % 160;    // h-group: covers h = 4*hg .. 4*hg+3
    const int cg   = tid / 160;    // 0..3: chunk sub-group (CPG/4 = 2 chunks each)

    __shared__ float sf[CPG];
    __shared__ float4 red[4][160];
    __shared__ unsigned int stick;
    __shared__ float sZ;

    const float* pbase = g_part + (size_t)b * MAXC * PSTRIDE;

    // warp 0: global max over all C chunk maxima, then f for this group's chunks
    if (wid == 0) {
        float m0 = -1e30f, m1 = -1e30f;
        if (lane < C)      m0 = pbase[(size_t)lane * PSTRIDE + 640];
        if (lane + 32 < C) m1 = pbase[(size_t)(lane + 32) * PSTRIDE + 640];
        float M = fmaxf(m0, m1);
        #pragma unroll
        for (int off = 16; off > 0; off >>= 1)
            M = fmaxf(M, __shfl_xor_sync(0xffffffffu, M, off));
        if (lane < CPG) {
            const float mc = pbase[(size_t)(cs * CPG + lane) * PSTRIDE + 640];
            sf[lane] = __expf(mc - M);
        }
        // total Z referenced to global M (every CTA computes it; only the
        // fixup CTA uses it, but it's 2 extra exp/lane — free)
        float z = 0.f;
        if (lane < C)      z += __expf(m0 - M) * pbase[(size_t)lane * PSTRIDE + 641];
        if (lane + 32 < C) z += __expf(m1 - M) * pbase[(size_t)(lane + 32) * PSTRIDE + 641];
        #pragma unroll
        for (int off = 16; off > 0; off >>= 1)
            z += __shfl_xor_sync(0xffffffffu, z, off);
        if (lane == 0) sZ = z;
    }
    __syncthreads();

    // each thread: float4 partial over its 2 chunks, fully coalesced
    float4 s = make_float4(0.f, 0.f, 0.f, 0.f);
    #pragma unroll
    for (int k = 0; k < CPG / 4; k++) {
        const int cl = cg * (CPG / 4) + k;
        const float f = sf[cl];
        const float4 v = *(const float4*)&pbase[(size_t)(cs * CPG + cl) * PSTRIDE + 4 * hg];
        s.x = fmaf(f, v.x, s.x);
        s.y = fmaf(f, v.y, s.y);
        s.z = fmaf(f, v.z, s.z);
        s.w = fmaf(f, v.w, s.w);
    }
    red[cg][hg] = s;
    __syncthreads();

    // c-group 0 threads reduce 4 partials and store
    if (tid < 160) {
        float4 a0 = red[0][tid], a1 = red[1][tid], a2 = red[2][tid], a3 = red[3][tid];
        a0.x += a1.x + a2.x + a3.x;
        a0.y += a1.y + a2.y + a3.y;
        a0.z += a1.z + a2.z + a3.z;
        a0.w += a1.w + a2.w + a3.w;
        *(float4*)&g_sbpart[((size_t)b * CSPLIT + cs) * HIDDEN + 4 * tid] = a0;
    }

    // ---- last-CTA fixup: reduce CSPLIT partials + normalize (L2-hot) ----
    __threadfence();
    __syncthreads();
    if (tid == 0) stick = atomicAdd(&g_cnt1[b], 1u);
    __syncthreads();
    if (stick == CSPLIT - 1) {
        const float invZ = 1.0f / sZ;
        float r = 0.f;
        #pragma unroll
        for (int g = 0; g < CSPLIT; g++)
            r += __ldcg(&g_sbpart[((size_t)b * CSPLIT + g) * HIDDEN + tid]);
        g_sb[b * HIDDEN + tid] = r * invZ;
        if (tid == 0) g_cnt1[b] = 0u;   // reset for next replay
    }
}

// ============================================================
// Kernel 2b: pooled[b][v] = g_sb[b] . Wv[v] for all b; last CTA per
// z-slice does the LayerNorm + output store (L2-hot).
// grid(HIDDEN/8, 1, ceil(B/BSLICE)), block(256) = 8 warps, warp-per-row.
// ============================================================
__global__ void __launch_bounds__(256)
k2b_gemv_ln(const float* __restrict__ Wv,
            const float* __restrict__ gamma,
            const float* __restrict__ beta,
            float* __restrict__ out, int B)
{
    __shared__ float sb_sm[BSLICE * HIDDEN];   // 40 KB
    __shared__ unsigned int stick;

    const int tid  = threadIdx.x;
    const int wid  = tid >> 5;
    const int lane = tid & 31;
    const int b0   = blockIdx.z * BSLICE;
    const int nb   = min(BSLICE, B - b0);
    const int v    = blockIdx.x * 8 + wid;

    for (int i = tid; i < nb * HIDDEN; i += 256)
        sb_sm[i] = g_sb[(size_t)b0 * HIDDEN + i];
    __syncthreads();

    float4 r[5];
    {
        const float4* wr = (const float4*)(Wv + (size_t)v * HIDDEN);
        #pragma unroll
        for (int j = 0; j < 5; j++) r[j] = wr[lane + 32 * j];
    }

    for (int b = 0; b < nb; b += 2) {
        const bool two = (b + 1 < nb);
        const float4* s0 = (const float4*)(sb_sm + (size_t)b * HIDDEN);
        const float4* s1 = (const float4*)(sb_sm + (size_t)(two ? b + 1 : b) * HIDDEN);
        float d0 = 0.f, d1 = 0.f;
        #pragma unroll
        for (int j = 0; j < 5; j++) {
            const float4 a0 = s0[lane + 32 * j];
            const float4 a1 = s1[lane + 32 * j];
            d0 = fmaf(r[j].x, a0.x, d0); d1 = fmaf(r[j].x, a1.x, d1);
            d0 = fmaf(r[j].y, a0.y, d0); d1 = fmaf(r[j].y, a1.y, d1);
            d0 = fmaf(r[j].z, a0.z, d0); d1 = fmaf(r[j].z, a1.z, d1);
            d0 = fmaf(r[j].w, a0.w, d0); d1 = fmaf(r[j].w, a1.w, d1);
        }
        #pragma unroll
        for (int off = 16; off > 0; off >>= 1) {
            d0 += __shfl_xor_sync(0xffffffffu, d0, off);
            d1 += __shfl_xor_sync(0xffffffffu, d1, off);
        }
        if (lane == 0) {
            g_pool[(size_t)(b0 + b) * HIDDEN + v] = d0;
            if (two) g_pool[(size_t)(b0 + b + 1) * HIDDEN + v] = d1;
        }
    }

    // ---- last-CTA fixup: LayerNorm + store (warp-per-batch, L2-hot) ----
    __threadfence();
    __syncthreads();
    if (tid == 0) stick = atomicAdd(&g_cnt2[blockIdx.z], 1u);
    __syncthreads();
    if (stick == gridDim.x - 1) {
        for (int bb = wid; bb < nb; bb += 8) {
            const int b = b0 + bb;
            float xv[HIDDEN / 32];
            float s = 0.f, q = 0.f;
            #pragma unroll
            for (int i = 0; i < HIDDEN / 32; i++) {
                xv[i] = __ldcg(&g_pool[(size_t)b * HIDDEN + lane + 32 * i]);
                s += xv[i];
                q = fmaf(xv[i], xv[i], q);
            }
            #pragma unroll
            for (int off = 16; off > 0; off >>= 1) {
                s += __shfl_xor_sync(0xffffffffu, s, off);
                q += __shfl_xor_sync(0xffffffffu, q, off);
            }
            const float mu   = s / (float)HIDDEN;
            const float var  = q / (float)HIDDEN - mu * mu;
            const float rstd = rsqrtf(var + LN_EPS);
            #pragma unroll
            for (int i = 0; i < HIDDEN / 32; i++) {
                const int h = lane + 32 * i;
                out[(size_t)b * HIDDEN + h] =
                    (xv[i] - mu) * rstd * gamma[h] + beta[h];
            }
        }
        if (tid == 0) g_cnt2[blockIdx.z] = 0u;   // reset for next replay
    }
}

// ============================================================
extern "C" void kernel_launch(void* const* d_in, const int* in_sizes, int n_in,
                              void* d_out, int out_size)
{
    const float* X     = (const float*)d_in[0];
    const float* pos   = (const float*)d_in[1];
    const float* Wq    = (const float*)d_in[2];
    const float* Wk    = (const float*)d_in[3];
    const float* Wv    = (const float*)d_in[4];
    const float* gamma = (const float*)d_in[5];
    const float* beta  = (const float*)d_in[6];
    float* out = (float*)d_out;

    const int B = in_sizes[1] / HIDDEN;
    const int N = in_sizes[0] / (B * HIDDEN);
    const int C = CHUNKS;
    const int chunk = (N + C - 1) / C;

    dim3 g0(B, GSPLIT);
    k0_make_w<<<g0, HIDDEN>>>(pos, Wq, Wk);
    dim3 g1(C, B);
    k1_stream<<<g1, WARPS * 32>>>(X, N, chunk);
    dim3 g2a(B, CSPLIT);
    k2a1_partial<<<g2a, HIDDEN>>>(C);
    dim3 g2b(HIDDEN / 8, 1, (B + BSLICE - 1) / BSLICE);
    k2b_gemv_ln<<<g2b, 256>>>(Wv, gamma, beta, out, B);
}